// round 7
// baseline (speedup 1.0000x reference)
#include <cuda_runtime.h>
#include <math.h>

#define BSZ  1024
#define TLEN 256
#define HH   128
#define GG   384   // 3*H

// -------- scratch (static device globals; no runtime allocation) --------
__device__ float g_gi[(size_t)BSZ * TLEN * GG];    // 402 MB, reused for gi0 then gi1
__device__ float g_seq[(size_t)BSZ * TLEN * HH];   // 134 MB, layer-0 output sequence
__device__ float g_hlast[(size_t)BSZ * HH];        // layer-1 final hidden

typedef unsigned long long u64;

// ---- packed f32x2 helpers (sm_100+; ptxas never auto-fuses these) ----
__device__ __forceinline__ void fma2(u64& d, u64 a, u64 b) {
    asm("fma.rn.f32x2 %0, %1, %2, %0;" : "+l"(d) : "l"(a), "l"(b));
}
__device__ __forceinline__ u64 pack2(float x) {
    u64 r; asm("mov.b64 %0, {%1, %1};" : "=l"(r) : "f"(x)); return r;
}
__device__ __forceinline__ float2 unpack2(u64 v) {
    float2 r; asm("mov.b64 {%0, %1}, %2;" : "=f"(r.x), "=f"(r.y) : "l"(v)); return r;
}

__device__ __forceinline__ float fsigmoid(float x) {
    return __fdividef(1.f, 1.f + __expf(-x));
}
__device__ __forceinline__ float ftanh(float x) {
    return 1.f - __fdividef(2.f, __expf(2.f * x) + 1.f);
}

// =======================================================================
// GEMM: g_gi[row][c] = sum_k X[row][k] * W[c][k] + bias[c]
// rows = 262144, N = 384, K in {153,128}. 64-row tile, 256 threads,
// thread tile 8 rows x 6 col-PAIRS, packed f32x2 FMA.
// x stored DUPLICATED ({x,x} u64) -> inner loop has no pack MOVs.
// =======================================================================
__global__ void __launch_bounds__(256) gemm384(
    const float* __restrict__ Xext, int useSeq, int K,
    const float* __restrict__ W, const float* __restrict__ bias)
{
    const float* __restrict__ X = useSeq ? g_seq : Xext;
    __shared__ float xs2[64][32];    // [row][2*kk] duplicated pairs
    __shared__ float ws[16][386];    // [kk][col], pad 386 -> conflict-free
    int tid = threadIdx.x;
    size_t row0 = (size_t)blockIdx.x * 64;
    int tr = (tid >> 5) * 8;     // thread row base within tile
    int tc = tid & 31;           // col-pair base; cols {2tc,2tc+1} + 64*j

    u64 acc[8][6];
#pragma unroll
    for (int r = 0; r < 8; r++)
#pragma unroll
        for (int j = 0; j < 6; j++) acc[r][j] = 0ull;

    for (int k0 = 0; k0 < K; k0 += 16) {
#pragma unroll
        for (int i = tid; i < 64 * 16; i += 256) {
            int r = i >> 4, kk = i & 15;
            int k = k0 + kk;
            float v = (k < K) ? X[(row0 + r) * (size_t)K + k] : 0.f;
            *(float2*)&xs2[r][2 * kk] = make_float2(v, v);
        }
#pragma unroll
        for (int i = tid; i < 384 * 16; i += 256) {
            int c = i >> 4, kk = i & 15;
            int k = k0 + kk;
            ws[kk][c] = (k < K) ? W[(size_t)c * K + k] : 0.f;
        }
        __syncthreads();
#pragma unroll
        for (int kk = 0; kk < 16; kk++) {
            u64 wv[6];
#pragma unroll
            for (int j = 0; j < 6; j++)
                wv[j] = *(const u64*)&ws[kk][2 * tc + 64 * j];
#pragma unroll
            for (int r = 0; r < 8; r++) {
                u64 xp = *(const u64*)&xs2[tr + r][2 * kk];  // broadcast LDS.64
#pragma unroll
                for (int j = 0; j < 6; j++)
                    fma2(acc[r][j], xp, wv[j]);
            }
        }
        __syncthreads();
    }
#pragma unroll
    for (int j = 0; j < 6; j++) {
        int c = 2 * tc + 64 * j;
        float2 bv = make_float2(bias[c], bias[c + 1]);
#pragma unroll
        for (int r = 0; r < 8; r++) {
            float2 v = unpack2(acc[r][j]);
            v.x += bv.x; v.y += bv.y;
            *(float2*)&g_gi[(row0 + tr + r) * (size_t)GG + c] = v;
        }
    }
}

// =======================================================================
// GRU recurrence v4. 128 CTAs x 8 batch rows; 256 threads, merged teams.
// All 8 warps do matvec (k-split 2-way: kh = tid>>7 owns 64 k's) AND gates.
// Thread owns 3 cols x 4 row-pairs (f32x2 accumulators, rows packed).
// Partial sums staged in ghsh[col][kh*8 + 2rp], summed by gate phase.
// smem: wk[128][384] + hp[4][256] + ghsh[384][18] = 223 KB
// =======================================================================
#define WK_STRIDE 384
#define GH_STRIDE 18   // odd/2 floats per col -> <=2-way conflicts, u64-aligned
#define RECUR_SMEM ((128 * WK_STRIDE + 4 * 128 * 2 + 384 * GH_STRIDE) * (int)sizeof(float))

__global__ void __launch_bounds__(256) gru_recur(
    const float* __restrict__ Whh, const float* __restrict__ bhh, int writeSeq)
{
    extern __shared__ float smem[];
    float* wk   = smem;                        // [128][384]: wk[k*384+g] = Whh[g][k]
    float* hp   = smem + 128 * WK_STRIDE;      // [4][256] row-pair dup: hp[rp*256+2k+(r&1)]
    float* ghsh = hp + 4 * 128 * 2;            // [384][18] partial gh per col

    int tid = threadIdx.x;
    size_t b0 = (size_t)blockIdx.x * 8;

    // load Whh transposed (one-time; STS conflicts acceptable)
    for (int idx = tid; idx < GG * HH; idx += 256) {
        int g = idx >> 7, k = idx & 127;
        wk[k * WK_STRIDE + g] = Whh[idx];
    }
    for (int idx = tid; idx < 4 * 128 * 2; idx += 256) hp[idx] = 0.f;

    // matvec mapping: k-half + 3 columns
    const int kh  = tid >> 7;                  // 0/1 -> k in [kh*64, kh*64+64)
    const int col = tid & 127;                 // cols col, col+128, col+256
    const int kbase = kh * 64;

    u64 bias2[3];
#pragma unroll
    for (int c = 0; c < 3; c++)
        bias2[c] = kh ? 0ull : pack2(bhh[col + 128 * c]);

    // gate mapping: row gr, units gl + 32u
    const int gr = tid >> 5;                   // 0..7
    const int gl = tid & 31;

    float hreg[4] = {0.f, 0.f, 0.f, 0.f};
    const float* gi_base = g_gi + ((b0 + gr) * TLEN) * (size_t)GG + gl;
    float* seq_base = g_seq + ((b0 + gr) * TLEN) * (size_t)HH + gl;

    const float* wrow = wk + kbase * WK_STRIDE + col;
    __syncthreads();

    for (int t = 0; t < TLEN; t++) {
        // gi prefetch: LDGs issue here, latency hidden under the matvec loop
        float gi_v[12];
        {
            const float* gp = gi_base + (size_t)t * GG;
#pragma unroll
            for (int gidx = 0; gidx < 3; gidx++)
#pragma unroll
                for (int u = 0; u < 4; u++)
                    gi_v[gidx * 4 + u] = gp[gidx * 128 + u * 32];
        }

        // ---- matvec partial: 32 k-pairs ----
        u64 acc[4][3];
#pragma unroll
        for (int rp = 0; rp < 4; rp++)
#pragma unroll
            for (int c = 0; c < 3; c++) acc[rp][c] = bias2[c];

#pragma unroll 4
        for (int kp = 0; kp < 32; kp++) {
            int k2 = 2 * kp;                   // local k offset (even)
            u64 wd0[3], wd1[3];
#pragma unroll
            for (int c = 0; c < 3; c++) {
                wd0[c] = pack2(wrow[(size_t)k2 * WK_STRIDE + 128 * c]);
                wd1[c] = pack2(wrow[(size_t)(k2 + 1) * WK_STRIDE + 128 * c]);
            }
#pragma unroll
            for (int rp = 0; rp < 4; rp++) {
                // {h_r0[k],h_r1[k],h_r0[k+1],h_r1[k+1]} broadcast LDS.128
                ulonglong2 h2 = *(const ulonglong2*)(hp + rp * 256 + 2 * (kbase + k2));
#pragma unroll
                for (int c = 0; c < 3; c++) {
                    fma2(acc[rp][c], h2.x, wd0[c]);
                    fma2(acc[rp][c], h2.y, wd1[c]);
                }
            }
        }
        // stage partials: ghsh[colg][kh*8 + 2rp] (u64, aligned: 18*4*col % 8 == 0)
#pragma unroll
        for (int c = 0; c < 3; c++)
#pragma unroll
            for (int rp = 0; rp < 4; rp++)
                *(u64*)(ghsh + (col + 128 * c) * GH_STRIDE + kh * 8 + 2 * rp) = acc[rp][c];
        __syncthreads();

        // ---- gates: sum the two k-partials, nonlinearity, h update ----
        {
            float hn[4];
#pragma unroll
            for (int u = 0; u < 4; u++) {
                int j = gl + 32 * u;
                const float* g0 = ghsh + j * GH_STRIDE + gr;
                const float* g1 = ghsh + (j + 128) * GH_STRIDE + gr;
                const float* g2 = ghsh + (j + 256) * GH_STRIDE + gr;
                float ghr = g0[0] + g0[8];
                float ghz = g1[0] + g1[8];
                float ghn = g2[0] + g2[8];
                float r = fsigmoid(gi_v[u] + ghr);
                float z = fsigmoid(gi_v[4 + u] + ghz);
                float n = ftanh(gi_v[8 + u] + r * ghn);
                hn[u] = (1.f - z) * n + z * hreg[u];
                hreg[u] = hn[u];
            }
            int rp = gr >> 1, half = gr & 1;
#pragma unroll
            for (int u = 0; u < 4; u++)
                hp[rp * 256 + 2 * (gl + 32 * u) + half] = hn[u];
            if (writeSeq) {
                float* sp = seq_base + (size_t)t * HH;
#pragma unroll
                for (int u = 0; u < 4; u++) sp[u * 32] = hn[u];
            }
        }
        __syncthreads();
    }

    if (!writeSeq) {
        float* hl = g_hlast + (b0 + gr) * HH + gl;
#pragma unroll
        for (int u = 0; u < 4; u++) hl[u * 32] = hreg[u];
    }
}

// =======================================================================
// Head: out[b] = sigmoid( relu(h_last[b] @ W1^T + b1) @ W2^T + b2 )
// =======================================================================
__global__ void __launch_bounds__(64) head_kernel(
    const float* __restrict__ W1, const float* __restrict__ b1,
    const float* __restrict__ W2, const float* __restrict__ b2,
    float* __restrict__ out)
{
    int b = blockIdx.x;
    int c = threadIdx.x;  // 0..63
    const float* hb = g_hlast + (size_t)b * HH;
    const float* wr = W1 + (size_t)c * HH;
    float acc = b1[c];
#pragma unroll
    for (int k = 0; k < HH; k += 4) {
        float4 hv = *(const float4*)(hb + k);
        float4 wv = *(const float4*)(wr + k);
        acc = fmaf(hv.x, wv.x, acc);
        acc = fmaf(hv.y, wv.y, acc);
        acc = fmaf(hv.z, wv.z, acc);
        acc = fmaf(hv.w, wv.w, acc);
    }
    float v = fmaxf(acc, 0.f) * W2[c];
    __shared__ float red[64];
    red[c] = v;
    __syncthreads();
    if (c == 0) {
        float s = b2[0];
#pragma unroll
        for (int i = 0; i < 64; i++) s += red[i];
        out[b] = 1.f / (1.f + expf(-s));
    }
}

// =======================================================================
extern "C" void kernel_launch(void* const* d_in, const int* in_sizes, int n_in,
                              void* d_out, int out_size)
{
    const float* x     = (const float*)d_in[0];
    const float* W_ih0 = (const float*)d_in[1];
    const float* W_hh0 = (const float*)d_in[2];
    const float* b_ih0 = (const float*)d_in[3];
    const float* b_hh0 = (const float*)d_in[4];
    const float* W_ih1 = (const float*)d_in[5];
    const float* W_hh1 = (const float*)d_in[6];
    const float* b_ih1 = (const float*)d_in[7];
    const float* b_hh1 = (const float*)d_in[8];
    const float* W1    = (const float*)d_in[9];
    const float* b1    = (const float*)d_in[10];
    const float* W2    = (const float*)d_in[11];
    const float* b2    = (const float*)d_in[12];
    float* out = (float*)d_out;

    cudaFuncSetAttribute(gru_recur, cudaFuncAttributeMaxDynamicSharedMemorySize,
                         RECUR_SMEM);

    const int M_TILES = (BSZ * TLEN) / 64;  // 4096

    gemm384<<<M_TILES, 256>>>(x, 0, 153, W_ih0, b_ih0);
    gru_recur<<<128, 256, RECUR_SMEM>>>(W_hh0, b_hh0, 1);
    gemm384<<<M_TILES, 256>>>(nullptr, 1, 128, W_ih1, b_ih1);
    gru_recur<<<128, 256, RECUR_SMEM>>>(W_hh1, b_hh1, 0);
    head_kernel<<<BSZ, 64>>>(W1, b1, W2, b2, out);
}